// round 2
// baseline (speedup 1.0000x reference)
#include <cuda_runtime.h>

#define BATCH 32
#define H 512
#define W 512
#define NPIX (H*W)
#define NITER 10

#define TX 128          // tile width (pixels)
#define TY 32           // tile height (pixels)
#define SW (TX + 2)     // smem tile width incl. halo
#define SH (TY + 2)     // smem tile height incl. halo
#define SSTR 132        // padded smem row stride (floats)

// Ping-pong scratch (allocation-free requirement -> __device__ globals).
__device__ float g_buf[2][BATCH * NPIX];
// Sanitized per-batch step counts, clamped to [0, NITER].
__device__ int g_t[BATCH];

// Decide whether the t buffer is int32 or int64 (reference does astype(int64),
// but JAX default x64=False makes it int32). int64 little-endian layout of
// values in [0,10) <=> every odd 32-bit word is 0 and every even word < 16.
__global__ void prep_t(const int* __restrict__ t32) {
    __shared__ int is64;
    if (threadIdx.x == 0) {
        int ok = 1;
        for (int i = 0; i < BATCH; i++)
            ok &= (t32[2 * i + 1] == 0) && ((unsigned)t32[2 * i] < 16u);
        is64 = ok;
    }
    __syncthreads();
    int b = threadIdx.x;
    if (b < BATCH) {
        int v = is64 ? t32[2 * b] : t32[b];
        g_t[b] = max(0, min(NITER, v));
    }
}

__device__ __forceinline__ void sort3(float& a, float& b, float& c) {
    float t;
    t = fminf(a, b); b = fmaxf(a, b); a = t;
    t = fminf(b, c); c = fmaxf(b, c); b = t;
    t = fminf(a, b); b = fmaxf(a, b); a = t;
}

__device__ __forceinline__ float med3(float a, float b, float c) {
    return fminf(fmaxf(a, b), fmaxf(fminf(a, b), c));
}

// One median-blur step for all batches still active at step j.
// Reads parity j&1 (or x when j==0), writes parity (j+1)&1.
__global__ __launch_bounds__(256) void median_iter(
    const float* __restrict__ x,
    int j)
{
    const int b = blockIdx.z;
    if (j >= g_t[b]) return;   // batch finished: no work, no copy

    const float* __restrict__ src = (j == 0) ? (x + (size_t)b * NPIX)
                                             : (g_buf[j & 1] + (size_t)b * NPIX);
    float* __restrict__ dst = g_buf[(j + 1) & 1] + (size_t)b * NPIX;

    __shared__ float s[SH * SSTR];

    const int x0 = blockIdx.x * TX;
    const int y0 = blockIdx.y * TY;

    // Cooperative load of tile + 1-pixel halo, edge-clamped.
    for (int idx = threadIdx.x; idx < SH * SW; idx += 256) {
        int ly = idx / SW;
        int lx = idx - ly * SW;
        int gy = y0 + ly - 1; gy = max(0, min(H - 1, gy));
        int gx = x0 + lx - 1; gx = max(0, min(W - 1, gx));
        s[ly * SSTR + lx] = src[gy * W + gx];
    }
    __syncthreads();

    // 32 rows x 8 threads/row; each thread does a 16-pixel horizontal strip
    // with sliding sorted-column reuse (3 new LDS + 16 FMNMX per pixel).
    const int row = threadIdx.x >> 3;          // 0..31
    const int seg = (threadIdx.x & 7) << 4;    // 0,16,...,112

    const float* r0 = s + (row + 0) * SSTR + seg;
    const float* r1 = s + (row + 1) * SSTR + seg;
    const float* r2 = s + (row + 2) * SSTR + seg;

    // Sorted triples for window columns at local x = seg and seg+1.
    float lA = r0[0], mA = r1[0], hA = r2[0];
    sort3(lA, mA, hA);
    float lB = r0[1], mB = r1[1], hB = r2[1];
    sort3(lB, mB, hB);

    float res[16];
#pragma unroll
    for (int i = 0; i < 16; i++) {
        float lC = r0[2 + i];
        float mC = r1[2 + i];
        float hC = r2[2 + i];
        sort3(lC, mC, hC);

        float lo = fmaxf(fmaxf(lA, lB), lC);   // max of column mins
        float hi = fminf(fminf(hA, hB), hC);   // min of column maxes
        float md = med3(mA, mB, mC);           // median of column medians
        res[i] = med3(lo, md, hi);             // exact median of 9

        lA = lB; mA = mB; hA = hB;
        lB = lC; mB = mC; hB = hC;
    }

    // Vectorized writeback (x0+seg is 16-aligned -> float4 aligned).
    float4* o = reinterpret_cast<float4*>(dst + (size_t)(y0 + row) * W + x0 + seg);
#pragma unroll
    for (int v = 0; v < 4; v++)
        o[v] = make_float4(res[4 * v + 0], res[4 * v + 1], res[4 * v + 2], res[4 * v + 3]);
}

// Final gather: batch b's result lives at parity (n&1) where n = g_t[b],
// or still in x if n == 0.
__global__ __launch_bounds__(256) void gather(
    const float* __restrict__ x,
    float* __restrict__ out)
{
    const int b = blockIdx.y;
    const int n = g_t[b];

    const float4* src = (n == 0)
        ? reinterpret_cast<const float4*>(x + (size_t)b * NPIX)
        : reinterpret_cast<const float4*>(g_buf[n & 1] + (size_t)b * NPIX);
    float4* o = reinterpret_cast<float4*>(out + (size_t)b * NPIX);

    for (int i = blockIdx.x * blockDim.x + threadIdx.x; i < NPIX / 4;
         i += gridDim.x * blockDim.x)
        o[i] = src[i];
}

extern "C" void kernel_launch(void* const* d_in, const int* in_sizes, int n_in,
                              void* d_out, int out_size)
{
    const float* x = (const float*)d_in[0];
    const int* traw = (const int*)d_in[1];
    // d_in[2] = kernel_size (3), d_in[3] = num_timesteps (10): compile-time here.

    prep_t<<<1, 32>>>(traw);

    dim3 grid(W / TX, H / TY, BATCH);   // (4, 16, 32)
    for (int j = 0; j < NITER; j++)
        median_iter<<<grid, 256>>>(x, j);

    gather<<<dim3(128, BATCH), 256>>>(x, (float*)d_out);
}

// round 4
// speedup vs baseline: 1.7487x; 1.7487x over previous
#include <cuda_runtime.h>

#define BATCH 32
#define H 512
#define W 512
#define NPIX (H*W)
#define NITER 10

#define TX 64
#define TY 32
#define IN_W 68     // TX + 4 (2-ring halo)
#define IN_H 36     // TY + 4
#define MID_W 66    // TX + 2
#define MID_H 34    // TY + 2
#define S1 69       // sIn stride: odd -> conflict-free across lanes (bank = 5*lane mod 32)
#define S2 67       // sMid stride: odd -> conflict-free (bank = 3*lane mod 32)

// Ping-pong scratch (allocation-free requirement -> __device__ globals).
__device__ __align__(16) float g_buf[2][BATCH * NPIX];
// Sanitized per-batch step counts, clamped to [0, NITER].
__device__ int g_t[BATCH];

// Decide whether the t buffer is int32 or int64 (reference does astype(int64),
// but JAX default x64=False makes it int32).
__global__ void prep_t(const int* __restrict__ t32) {
    __shared__ int is64;
    if (threadIdx.x == 0) {
        int ok = 1;
        for (int i = 0; i < BATCH; i++)
            ok &= (t32[2 * i + 1] == 0) && ((unsigned)t32[2 * i] < 16u);
        is64 = ok;
    }
    __syncthreads();
    int b = threadIdx.x;
    if (b < BATCH) {
        int v = is64 ? t32[2 * b] : t32[b];
        g_t[b] = max(0, min(NITER, v));
    }
}

__device__ __forceinline__ void sort3(float& a, float& b, float& c) {
    float t;
    t = fminf(a, b); b = fmaxf(a, b); a = t;
    t = fminf(b, c); c = fmaxf(b, c); b = t;
    t = fminf(a, b); b = fmaxf(a, b); a = t;
}

__device__ __forceinline__ float med3(float a, float b, float c) {
    return fminf(fmaxf(a, b), fmaxf(fminf(a, b), c));
}

// N medians from a 3-row strip using sliding sorted-column reuse.
template<int N>
__device__ __forceinline__ void med_strip(const float* __restrict__ r0,
                                          const float* __restrict__ r1,
                                          const float* __restrict__ r2,
                                          float* __restrict__ res) {
    float lA = r0[0], mA = r1[0], hA = r2[0]; sort3(lA, mA, hA);
    float lB = r0[1], mB = r1[1], hB = r2[1]; sort3(lB, mB, hB);
#pragma unroll
    for (int i = 0; i < N; i++) {
        float lC = r0[2 + i], mC = r1[2 + i], hC = r2[2 + i];
        sort3(lC, mC, hC);
        float lo = fmaxf(fmaxf(lA, lB), lC);   // max of column mins
        float hi = fminf(fminf(hA, hB), hC);   // min of column maxes
        float md = med3(mA, mB, mC);           // median of column medians
        res[i] = med3(lo, md, hi);             // exact median of 9
        lA = lB; mA = mB; hA = hB;
        lB = lC; mB = mC; hB = hC;
    }
}

// Two fused median-blur steps (global steps j=2s and j=2s+1).
__global__ __launch_bounds__(256) void fused2(const float* __restrict__ x,
                                              float* __restrict__ out, int s) {
    const int b = blockIdx.z;
    const int tb = g_t[b];
    const int j = 2 * s;
    if (tb <= j) return;

    const float* __restrict__ src =
        (s == 0) ? x + (size_t)b * NPIX : g_buf[s & 1] + (size_t)b * NPIX;

    __shared__ float sIn[IN_H * S1];
    __shared__ float sMid[MID_H * S2];

    const int x0 = blockIdx.x * TX;
    const int y0 = blockIdx.y * TY;

    // Cooperative load of tile + 2-ring halo, edge-clamped.
    for (int idx = threadIdx.x; idx < IN_H * IN_W; idx += 256) {
        int ly = idx / IN_W, lx = idx - ly * IN_W;
        int gy = min(H - 1, max(0, y0 + ly - 2));
        int gx = min(W - 1, max(0, x0 + lx - 2));
        sIn[ly * S1 + lx] = src[gy * W + gx];
    }
    __syncthreads();

    const int lane = threadIdx.x & 31;   // output row within tile
    const int w = threadIdx.x >> 5;      // warp -> 8-px column segment

    if (tb == j + 1) {
        // Exactly one more step needed: single median on interior, final -> out.
        float res[8];
        const float* r0 = sIn + (lane + 1) * S1 + 8 * w + 1;
        med_strip<8>(r0, r0 + S1, r0 + 2 * S1, res);
        float4* o = (float4*)(out + (size_t)b * NPIX + (size_t)(y0 + lane) * W + x0 + 8 * w);
        o[0] = make_float4(res[0], res[1], res[2], res[3]);
        o[1] = make_float4(res[4], res[5], res[6], res[7]);
        return;
    }

    // Phase A: sMid[r][c] = median of sIn[r..r+2][c..c+2],
    // i.e. first-pass median centered at global (y0+r-1, x0+c-1).
    {
        const int c0 = 9 * w;            // 0,9,...,63
        float res[9];
        const float* r0 = sIn + lane * S1 + c0;
        med_strip<9>(r0, r0 + S1, r0 + 2 * S1, res);
        float* m = sMid + lane * S2 + c0;
#pragma unroll
        for (int i = 0; i < 9; i++)
            if (c0 + i < MID_W) m[i] = res[i];

        // Tail rows 32,33: one pixel per thread (132 px total).
        if (threadIdx.x < 2 * MID_W) {
            int second = threadIdx.x >= MID_W;
            int r = 32 + second;
            int c = threadIdx.x - (second ? MID_W : 0);
            const float* q0 = sIn + r * S1 + c;
            const float* q1 = q0 + S1;
            const float* q2 = q1 + S1;
            float a0 = q0[0], b0 = q1[0], c0v = q2[0]; sort3(a0, b0, c0v);
            float a1 = q0[1], b1 = q1[1], c1v = q2[1]; sort3(a1, b1, c1v);
            float a2 = q0[2], b2 = q1[2], c2v = q2[2]; sort3(a2, b2, c2v);
            float lo = fmaxf(fmaxf(a0, a1), a2);
            float hi = fminf(fminf(c0v, c1v), c2v);
            float md = med3(b0, b1, b2);
            sMid[r * S2 + c] = med3(lo, md, hi);
        }
    }
    __syncthreads();

    // Border fix: the intermediate must be edge-padded at the MID level
    // (mid[-1] = mid[0]), not derived from double-clamped input. Replicate
    // sMid's halo rows/cols from the adjacent valid row/col for border tiles.
    // Rows first, then columns (columns pick up fixed corners) = per-axis clamp.
    if (y0 == 0)
        for (int c = threadIdx.x; c < MID_W; c += 256) sMid[c] = sMid[S2 + c];
    if (y0 + TY == H)
        for (int c = threadIdx.x; c < MID_W; c += 256)
            sMid[(MID_H - 1) * S2 + c] = sMid[(MID_H - 2) * S2 + c];
    __syncthreads();
    if (x0 == 0)
        for (int r = threadIdx.x; r < MID_H; r += 256) sMid[r * S2] = sMid[r * S2 + 1];
    if (x0 + TX == W)
        for (int r = threadIdx.x; r < MID_H; r += 256)
            sMid[r * S2 + MID_W - 1] = sMid[r * S2 + MID_W - 2];
    __syncthreads();

    // Phase B: final tile from sMid. Finishers (tb == j+2) go straight to out.
    {
        float* dstbase = (tb == j + 2) ? out + (size_t)b * NPIX
                                       : g_buf[(s + 1) & 1] + (size_t)b * NPIX;
        float res[8];
        const float* m0 = sMid + lane * S2 + 8 * w;
        med_strip<8>(m0, m0 + S2, m0 + 2 * S2, res);
        float4* o = (float4*)(dstbase + (size_t)(y0 + lane) * W + x0 + 8 * w);
        o[0] = make_float4(res[0], res[1], res[2], res[3]);
        o[1] = make_float4(res[4], res[5], res[6], res[7]);
    }
}

// Only batches with t == 0 still need their output (a copy of x).
__global__ __launch_bounds__(256) void gather0(const float* __restrict__ x,
                                               float* __restrict__ out) {
    const int b = blockIdx.y;
    if (g_t[b] != 0) return;
    const float4* src = (const float4*)(x + (size_t)b * NPIX);
    float4* o = (float4*)(out + (size_t)b * NPIX);
    for (int i = blockIdx.x * blockDim.x + threadIdx.x; i < NPIX / 4;
         i += gridDim.x * blockDim.x)
        o[i] = src[i];
}

extern "C" void kernel_launch(void* const* d_in, const int* in_sizes, int n_in,
                              void* d_out, int out_size)
{
    const float* x = (const float*)d_in[0];
    const int* traw = (const int*)d_in[1];
    float* out = (float*)d_out;

    prep_t<<<1, 32>>>(traw);

    dim3 grid(W / TX, H / TY, BATCH);   // (8, 16, 32)
    for (int s = 0; s < NITER / 2; s++)
        fused2<<<grid, 256>>>(x, out, s);

    gather0<<<dim3(64, BATCH), 256>>>(x, out);
}

// round 5
// speedup vs baseline: 1.7617x; 1.0074x over previous
#include <cuda_runtime.h>

#define BATCH 32
#define H 512
#define W 512
#define NPIX (H*W)
#define NITER 10

#define TX 64
#define TY 32
#define IN_W 68     // TX + 4 (2-ring halo)
#define IN_H 36     // TY + 4
#define MID_W 66    // TX + 2
#define MID_H 34    // TY + 2
#define S1 69       // sIn stride: odd -> conflict-free across lanes (bank = 5*lane mod 32)
#define S2 67       // sMid stride: odd -> conflict-free (bank = 3*lane mod 32)

// Ping-pong scratch (allocation-free requirement -> __device__ globals).
__device__ __align__(16) float g_buf[2][BATCH * NPIX];
// Sanitized per-batch step counts, clamped to [0, NITER].
__device__ int g_t[BATCH];

// Decide whether the t buffer is int32 or int64 (reference does astype(int64),
// but JAX default x64=False makes it int32).
__global__ void prep_t(const int* __restrict__ t32) {
    __shared__ int is64;
    if (threadIdx.x == 0) {
        int ok = 1;
        for (int i = 0; i < BATCH; i++)
            ok &= (t32[2 * i + 1] == 0) && ((unsigned)t32[2 * i] < 16u);
        is64 = ok;
    }
    __syncthreads();
    int b = threadIdx.x;
    if (b < BATCH) {
        int v = is64 ? t32[2 * b] : t32[b];
        g_t[b] = max(0, min(NITER, v));
    }
}

__device__ __forceinline__ void sort3(float& a, float& b, float& c) {
    float t;
    t = fminf(a, b); b = fmaxf(a, b); a = t;
    t = fminf(b, c); c = fmaxf(b, c); b = t;
    t = fminf(a, b); b = fmaxf(a, b); a = t;
}

__device__ __forceinline__ float med3(float a, float b, float c) {
    return fminf(fmaxf(a, b), fmaxf(fminf(a, b), c));
}

// N medians from a 3-row strip using sliding sorted-column reuse.
template<int N>
__device__ __forceinline__ void med_strip(const float* __restrict__ r0,
                                          const float* __restrict__ r1,
                                          const float* __restrict__ r2,
                                          float* __restrict__ res) {
    float lA = r0[0], mA = r1[0], hA = r2[0]; sort3(lA, mA, hA);
    float lB = r0[1], mB = r1[1], hB = r2[1]; sort3(lB, mB, hB);
#pragma unroll
    for (int i = 0; i < N; i++) {
        float lC = r0[2 + i], mC = r1[2 + i], hC = r2[2 + i];
        sort3(lC, mC, hC);
        float lo = fmaxf(fmaxf(lA, lB), lC);   // max of column mins
        float hi = fminf(fminf(hA, hB), hC);   // min of column maxes
        float md = med3(mA, mB, mC);           // median of column medians
        res[i] = med3(lo, md, hi);             // exact median of 9
        lA = lB; mA = mB; hA = hB;
        lB = lC; mB = mC; hB = hC;
    }
}

// Two fused median-blur steps (global steps j=2s and j=2s+1).
__global__ __launch_bounds__(256) void fused2(const float* __restrict__ x,
                                              float* __restrict__ out, int s) {
    const int b = blockIdx.z;
    const int tb = g_t[b];
    const int j = 2 * s;
    if (tb <= j) return;

    const float* __restrict__ src =
        (s == 0) ? x + (size_t)b * NPIX : g_buf[s & 1] + (size_t)b * NPIX;

    __shared__ float sIn[IN_H * S1];
    __shared__ float sMid[MID_H * S2];

    const int x0 = blockIdx.x * TX;
    const int y0 = blockIdx.y * TY;

    // Cooperative load of tile + 2-ring halo, edge-clamped.
    for (int idx = threadIdx.x; idx < IN_H * IN_W; idx += 256) {
        int ly = idx / IN_W, lx = idx - ly * IN_W;
        int gy = min(H - 1, max(0, y0 + ly - 2));
        int gx = min(W - 1, max(0, x0 + lx - 2));
        sIn[ly * S1 + lx] = src[gy * W + gx];
    }
    __syncthreads();

    const int lane = threadIdx.x & 31;   // output row within tile
    const int w = threadIdx.x >> 5;      // warp -> 8-px column segment

    if (tb == j + 1) {
        // Exactly one more step needed: single median on interior, final -> out.
        float res[8];
        const float* r0 = sIn + (lane + 1) * S1 + 8 * w + 1;
        med_strip<8>(r0, r0 + S1, r0 + 2 * S1, res);
        float4* o = (float4*)(out + (size_t)b * NPIX + (size_t)(y0 + lane) * W + x0 + 8 * w);
        o[0] = make_float4(res[0], res[1], res[2], res[3]);
        o[1] = make_float4(res[4], res[5], res[6], res[7]);
        return;
    }

    // Phase A: sMid[r][c] = median of sIn[r..r+2][c..c+2],
    // i.e. first-pass median centered at global (y0+r-1, x0+c-1).
    {
        const int c0 = 9 * w;            // 0,9,...,63
        float res[9];
        const float* r0 = sIn + lane * S1 + c0;
        med_strip<9>(r0, r0 + S1, r0 + 2 * S1, res);
        float* m = sMid + lane * S2 + c0;
#pragma unroll
        for (int i = 0; i < 9; i++)
            if (c0 + i < MID_W) m[i] = res[i];

        // Tail rows 32,33: one pixel per thread (132 px total).
        if (threadIdx.x < 2 * MID_W) {
            int second = threadIdx.x >= MID_W;
            int r = 32 + second;
            int c = threadIdx.x - (second ? MID_W : 0);
            const float* q0 = sIn + r * S1 + c;
            const float* q1 = q0 + S1;
            const float* q2 = q1 + S1;
            float a0 = q0[0], b0 = q1[0], c0v = q2[0]; sort3(a0, b0, c0v);
            float a1 = q0[1], b1 = q1[1], c1v = q2[1]; sort3(a1, b1, c1v);
            float a2 = q0[2], b2 = q1[2], c2v = q2[2]; sort3(a2, b2, c2v);
            float lo = fmaxf(fmaxf(a0, a1), a2);
            float hi = fminf(fminf(c0v, c1v), c2v);
            float md = med3(b0, b1, b2);
            sMid[r * S2 + c] = med3(lo, md, hi);
        }
    }
    __syncthreads();

    // Border fix: the intermediate must be edge-padded at the MID level
    // (mid[-1] = mid[0]), not derived from double-clamped input. Replicate
    // sMid's halo rows/cols from the adjacent valid row/col for border tiles.
    // Rows first, then columns (columns pick up fixed corners) = per-axis clamp.
    if (y0 == 0)
        for (int c = threadIdx.x; c < MID_W; c += 256) sMid[c] = sMid[S2 + c];
    if (y0 + TY == H)
        for (int c = threadIdx.x; c < MID_W; c += 256)
            sMid[(MID_H - 1) * S2 + c] = sMid[(MID_H - 2) * S2 + c];
    __syncthreads();
    if (x0 == 0)
        for (int r = threadIdx.x; r < MID_H; r += 256) sMid[r * S2] = sMid[r * S2 + 1];
    if (x0 + TX == W)
        for (int r = threadIdx.x; r < MID_H; r += 256)
            sMid[r * S2 + MID_W - 1] = sMid[r * S2 + MID_W - 2];
    __syncthreads();

    // Phase B: final tile from sMid. Finishers (tb == j+2) go straight to out.
    {
        float* dstbase = (tb == j + 2) ? out + (size_t)b * NPIX
                                       : g_buf[(s + 1) & 1] + (size_t)b * NPIX;
        float res[8];
        const float* m0 = sMid + lane * S2 + 8 * w;
        med_strip<8>(m0, m0 + S2, m0 + 2 * S2, res);
        float4* o = (float4*)(dstbase + (size_t)(y0 + lane) * W + x0 + 8 * w);
        o[0] = make_float4(res[0], res[1], res[2], res[3]);
        o[1] = make_float4(res[4], res[5], res[6], res[7]);
    }
}

// Only batches with t == 0 still need their output (a copy of x).
__global__ __launch_bounds__(256) void gather0(const float* __restrict__ x,
                                               float* __restrict__ out) {
    const int b = blockIdx.y;
    if (g_t[b] != 0) return;
    const float4* src = (const float4*)(x + (size_t)b * NPIX);
    float4* o = (float4*)(out + (size_t)b * NPIX);
    for (int i = blockIdx.x * blockDim.x + threadIdx.x; i < NPIX / 4;
         i += gridDim.x * blockDim.x)
        o[i] = src[i];
}

extern "C" void kernel_launch(void* const* d_in, const int* in_sizes, int n_in,
                              void* d_out, int out_size)
{
    const float* x = (const float*)d_in[0];
    const int* traw = (const int*)d_in[1];
    float* out = (float*)d_out;

    prep_t<<<1, 32>>>(traw);

    dim3 grid(W / TX, H / TY, BATCH);   // (8, 16, 32)
    for (int s = 0; s < NITER / 2; s++)
        fused2<<<grid, 256>>>(x, out, s);

    gather0<<<dim3(64, BATCH), 256>>>(x, out);
}

// round 6
// speedup vs baseline: 2.1561x; 1.2238x over previous
#include <cuda_runtime.h>
#include <cuda_fp16.h>

#define BATCH 32
#define H 512
#define W 512
#define NPIX (H*W)
#define NITER 10

#define TX 128
#define TY 64
#define NT 512

// sIn2: packed pairs (in[y0+k], in[y0+k+32]), k in [-2,34), cols [-2,130).
#define A_ROWS 36
#define A_COLS 132
#define SA 133          // odd stride (half2 units) -> conflict-free
// sMid2: pairs (mid[p-1], mid[p+31]), p in [0,34), cols [-1,129).
#define B_ROWS 34
#define B_COLS 130
#define SB 131          // odd stride

// Ping-pong fp16 state (allocation-free requirement -> __device__ globals).
__device__ __align__(16) __half g_h[2][BATCH * NPIX];
__device__ int g_t[BATCH];

// Decide whether the t buffer is int32 or int64 (reference does astype(int64),
// but JAX default x64=False makes it int32).
__global__ void prep_t(const int* __restrict__ t32) {
    __shared__ int is64;
    if (threadIdx.x == 0) {
        int ok = 1;
        for (int i = 0; i < BATCH; i++)
            ok &= (t32[2 * i + 1] == 0) && ((unsigned)t32[2 * i] < 16u);
        is64 = ok;
    }
    __syncthreads();
    int b = threadIdx.x;
    if (b < BATCH) {
        int v = is64 ? t32[2 * b] : t32[b];
        g_t[b] = max(0, min(NITER, v));
    }
}

__device__ __forceinline__ void sort3h(__half2& a, __half2& b, __half2& c) {
    __half2 t;
    t = __hmin2(a, b); b = __hmax2(a, b); a = t;
    t = __hmin2(b, c); c = __hmax2(b, c); b = t;
    t = __hmin2(a, b); b = __hmax2(a, b); a = t;
}
__device__ __forceinline__ __half2 med3h(__half2 a, __half2 b, __half2 c) {
    return __hmin2(__hmax2(a, b), __hmax2(__hmin2(a, b), c));
}

// N packed medians from a 3-base strip (each lane = one image row),
// sliding sorted-column reuse: 3 LDS + 6 HMNMX2 per new column, 10 merge.
template<int N>
__device__ __forceinline__ void med_strip2(const __half2* __restrict__ r0,
                                           const __half2* __restrict__ r1,
                                           const __half2* __restrict__ r2,
                                           __half2* __restrict__ res) {
    __half2 lA = r0[0], mA = r1[0], hA = r2[0]; sort3h(lA, mA, hA);
    __half2 lB = r0[1], mB = r1[1], hB = r2[1]; sort3h(lB, mB, hB);
#pragma unroll
    for (int i = 0; i < N; i++) {
        __half2 lC = r0[2 + i], mC = r1[2 + i], hC = r2[2 + i];
        sort3h(lC, mC, hC);
        __half2 lo = __hmax2(__hmax2(lA, lB), lC);
        __half2 hi = __hmin2(__hmin2(hA, hB), hC);
        __half2 md = med3h(mA, mB, mC);
        res[i] = med3h(lo, md, hi);
        lA = lB; mA = mB; hA = hB;
        lB = lC; mB = mC; hB = hC;
    }
}

// Unpack 8 packed results into two fp32 rows (low lane -> o0, high -> o1).
__device__ __forceinline__ void store_rows_f32(float* o0, float* o1,
                                               const __half2* res) {
    float2 p0 = __half22float2(__lows2half2(res[0], res[1]));
    float2 p1 = __half22float2(__lows2half2(res[2], res[3]));
    float2 p2 = __half22float2(__lows2half2(res[4], res[5]));
    float2 p3 = __half22float2(__lows2half2(res[6], res[7]));
    ((float4*)o0)[0] = make_float4(p0.x, p0.y, p1.x, p1.y);
    ((float4*)o0)[1] = make_float4(p2.x, p2.y, p3.x, p3.y);
    p0 = __half22float2(__highs2half2(res[0], res[1]));
    p1 = __half22float2(__highs2half2(res[2], res[3]));
    p2 = __half22float2(__highs2half2(res[4], res[5]));
    p3 = __half22float2(__highs2half2(res[6], res[7]));
    ((float4*)o1)[0] = make_float4(p0.x, p0.y, p1.x, p1.y);
    ((float4*)o1)[1] = make_float4(p2.x, p2.y, p3.x, p3.y);
}

// Same but into two fp16 rows.
__device__ __forceinline__ void store_rows_h(__half* o0, __half* o1,
                                             const __half2* res) {
    union { uint4 u; __half2 h[4]; } pk;
    pk.h[0] = __lows2half2(res[0], res[1]);
    pk.h[1] = __lows2half2(res[2], res[3]);
    pk.h[2] = __lows2half2(res[4], res[5]);
    pk.h[3] = __lows2half2(res[6], res[7]);
    *(uint4*)o0 = pk.u;
    pk.h[0] = __highs2half2(res[0], res[1]);
    pk.h[1] = __highs2half2(res[2], res[3]);
    pk.h[2] = __highs2half2(res[4], res[5]);
    pk.h[3] = __highs2half2(res[6], res[7]);
    *(uint4*)o1 = pk.u;
}

// Two fused median-blur steps (global steps j=2s and j=2s+1), fp16x2-packed.
__global__ __launch_bounds__(NT) void fused2h(const float* __restrict__ x,
                                              float* __restrict__ out, int s) {
    const int b = blockIdx.z;
    const int tb = g_t[b];
    const int j = 2 * s;
    if (tb <= j) return;

    __shared__ __half2 sIn2[A_ROWS * SA + 16];   // +pad for masked strip overreads
    __shared__ __half2 sMid2[B_ROWS * SB];

    const int x0 = blockIdx.x * TX;
    const int y0 = blockIdx.y * TY;
    const int t = threadIdx.x;

    // ---- Load packed vertical pairs, edge-clamped (cvt fp32->fp16 at s==0).
    if (s == 0) {
        const float* src = x + (size_t)b * NPIX;
        for (int idx = t; idx < A_ROWS * A_COLS; idx += NT) {
            int a = idx / A_COLS, c = idx - a * A_COLS;
            int gy0 = min(H - 1, max(0, y0 + a - 2));
            int gy1 = min(H - 1, y0 + a + 30);
            int gx = min(W - 1, max(0, x0 + c - 2));
            sIn2[a * SA + c] = __floats2half2_rn(src[gy0 * W + gx], src[gy1 * W + gx]);
        }
    } else {
        const __half* src = g_h[s & 1] + (size_t)b * NPIX;
        for (int idx = t; idx < A_ROWS * A_COLS; idx += NT) {
            int a = idx / A_COLS, c = idx - a * A_COLS;
            int gy0 = min(H - 1, max(0, y0 + a - 2));
            int gy1 = min(H - 1, y0 + a + 30);
            int gx = min(W - 1, max(0, x0 + c - 2));
            sIn2[a * SA + c] = __halves2half2(src[gy0 * W + gx], src[gy1 * W + gx]);
        }
    }
    __syncthreads();

    const int q = t & 31;        // row base within warp: 32 distinct banks
    const int seg = t >> 5;      // 8-px column segment, one per warp

    if (tb == j + 1) {
        // Exactly one more step: single median on interior, final -> out.
        __half2 res[8];
        const __half2* r0 = sIn2 + (q + 1) * SA + 8 * seg + 1;
        med_strip2<8>(r0, r0 + SA, r0 + 2 * SA, res);
        float* o0 = out + (size_t)b * NPIX + (size_t)(y0 + q) * W + x0 + 8 * seg;
        store_rows_f32(o0, o0 + 32 * W, res);
        return;
    }

    // ---- Phase A: sMid2[p][c] = (mid[p-1], mid[p+31]) at mid col c-1.
    if (t < 510) {                       // 34 bases x 15 nine-col segments
        int qa = t % 34;
        int sa = t / 34;
        int c0 = 9 * sa;
        const __half2* r0 = sIn2 + qa * SA + c0;
        __half2 res[9];
        med_strip2<9>(r0, r0 + SA, r0 + 2 * SA, res);
        __half2* m = sMid2 + qa * SB + c0;
#pragma unroll
        for (int i = 0; i < 9; i++)
            if (c0 + i < B_COLS) m[i] = res[i];
    }
    __syncthreads();

    // ---- Mid-level edge padding (reference pads the intermediate, per axis).
    if (y0 == 0)                          // mid[-1] := mid[0] (low lanes)
        for (int c = t; c < B_COLS; c += NT) {
            __half2 v0 = sMid2[c], v1 = sMid2[SB + c];
            sMid2[c] = __halves2half2(__low2half(v1), __high2half(v0));
        }
    if (y0 + TY == H)                     // mid[64] := mid[63] (high lanes)
        for (int c = t; c < B_COLS; c += NT) {
            __half2 v33 = sMid2[33 * SB + c], v32 = sMid2[32 * SB + c];
            sMid2[33 * SB + c] = __halves2half2(__low2half(v33), __high2half(v32));
        }
    __syncthreads();
    if (x0 == 0)
        for (int p = t; p < B_ROWS; p += NT) sMid2[p * SB] = sMid2[p * SB + 1];
    if (x0 + TX == W)
        for (int p = t; p < B_ROWS; p += NT)
            sMid2[p * SB + B_COLS - 1] = sMid2[p * SB + B_COLS - 2];
    __syncthreads();

    // ---- Phase B: final tile. Finishers (tb == j+2) go straight to out.
    {
        __half2 res[8];
        const __half2* m0 = sMid2 + q * SB + 8 * seg;
        med_strip2<8>(m0, m0 + SB, m0 + 2 * SB, res);
        size_t off = (size_t)b * NPIX + (size_t)(y0 + q) * W + x0 + 8 * seg;
        if (tb == j + 2) {
            float* o0 = out + off;
            store_rows_f32(o0, o0 + 32 * W, res);
        } else {
            __half* o0 = g_h[(s + 1) & 1] + off;
            store_rows_h(o0, o0 + 32 * W, res);
        }
    }
}

// Only batches with t == 0 still need their output (a copy of x).
__global__ __launch_bounds__(256) void gather0(const float* __restrict__ x,
                                               float* __restrict__ out) {
    const int b = blockIdx.y;
    if (g_t[b] != 0) return;
    const float4* src = (const float4*)(x + (size_t)b * NPIX);
    float4* o = (float4*)(out + (size_t)b * NPIX);
    for (int i = blockIdx.x * blockDim.x + threadIdx.x; i < NPIX / 4;
         i += gridDim.x * blockDim.x)
        o[i] = src[i];
}

extern "C" void kernel_launch(void* const* d_in, const int* in_sizes, int n_in,
                              void* d_out, int out_size)
{
    const float* x = (const float*)d_in[0];
    const int* traw = (const int*)d_in[1];
    float* out = (float*)d_out;

    prep_t<<<1, 32>>>(traw);

    dim3 grid(W / TX, H / TY, BATCH);   // (4, 8, 32)
    for (int s = 0; s < NITER / 2; s++)
        fused2h<<<grid, NT>>>(x, out, s);

    gather0<<<dim3(64, BATCH), 256>>>(x, out);
}

// round 7
// speedup vs baseline: 2.8192x; 1.3076x over previous
#include <cuda_runtime.h>
#include <cuda_fp16.h>

#define BATCH 32
#define H 512
#define W 512
#define NPIX (H*W)
#define NITER 10

#define TX 128
#define TY 64
#define NT 512

// Packed-pair smem buffer: entry(k,c) = (row y0+k, row y0+k+32) at col x0+c,
// k in [-10,42), c in [-10,138). Stored at sB[(k+10)*SS + (c+10)].
#define SS 149          // odd stride (half2 units) -> conflict-free
#define RMAX 52

__device__ int g_t[BATCH];

// Decide whether the t buffer is int32 or int64 (reference does astype(int64),
// but JAX default x64=False makes it int32).
__global__ void prep_t(const int* __restrict__ t32) {
    __shared__ int is64;
    if (threadIdx.x == 0) {
        int ok = 1;
        for (int i = 0; i < BATCH; i++)
            ok &= (t32[2 * i + 1] == 0) && ((unsigned)t32[2 * i] < 16u);
        is64 = ok;
    }
    __syncthreads();
    int b = threadIdx.x;
    if (b < BATCH) {
        int v = is64 ? t32[2 * b] : t32[b];
        g_t[b] = max(0, min(NITER, v));
    }
}

__device__ __forceinline__ void sort3h(__half2& a, __half2& b, __half2& c) {
    __half2 t;
    t = __hmin2(a, b); b = __hmax2(a, b); a = t;
    t = __hmin2(b, c); c = __hmax2(b, c); b = t;
    t = __hmin2(a, b); b = __hmax2(a, b); a = t;
}
__device__ __forceinline__ __half2 med3h(__half2 a, __half2 b, __half2 c) {
    return __hmin2(__hmax2(a, b), __hmax2(__hmin2(a, b), c));
}

// 9 packed medians from a 3-row strip; r0/r1/r2 point at the first window col.
__device__ __forceinline__ void med_strip9(const __half2* __restrict__ r0,
                                           const __half2* __restrict__ r1,
                                           const __half2* __restrict__ r2,
                                           __half2* __restrict__ res) {
    __half2 lA = r0[0], mA = r1[0], hA = r2[0]; sort3h(lA, mA, hA);
    __half2 lB = r0[1], mB = r1[1], hB = r2[1]; sort3h(lB, mB, hB);
#pragma unroll
    for (int i = 0; i < 9; i++) {
        __half2 lC = r0[2 + i], mC = r1[2 + i], hC = r2[2 + i];
        sort3h(lC, mC, hC);
        __half2 lo = __hmax2(__hmax2(lA, lB), lC);
        __half2 hi = __hmin2(__hmin2(hA, hB), hC);
        __half2 md = med3h(mA, mB, mC);
        res[i] = med3h(lo, md, hi);
        lA = lB; mA = mB; hA = hB;
        lB = lC; mB = mC; hB = hC;
    }
}

// All n = g_t[b] median steps for one 128x64 tile, entirely in shared memory.
__global__ __launch_bounds__(NT, 3) void medianAll(const float* __restrict__ x,
                                                   float* __restrict__ out) {
    const int b = blockIdx.z;
    const int n = g_t[b];
    const int x0 = blockIdx.x * TX;
    const int y0 = blockIdx.y * TY;
    const float* __restrict__ src = x + (size_t)b * NPIX;
    float* __restrict__ dst = out + (size_t)b * NPIX;
    const int t = threadIdx.x;

    if (n == 0) {           // identity: copy tile
        for (int idx = t; idx < TY * (TX / 4); idx += NT) {
            int r = idx >> 5, cq = idx & 31;
            ((float4*)(dst + (size_t)(y0 + r) * W + x0))[cq] =
                ((const float4*)(src + (size_t)(y0 + r) * W + x0))[cq];
        }
        return;
    }

    __shared__ __half2 sB[RMAX * SS];

    // ---- Load packed pairs with n-deep halo, edge-clamped (== level-0 pad).
    const int rows_in = 32 + 2 * n, cols_in = 128 + 2 * n;
    for (int idx = t; idx < rows_in * cols_in; idx += NT) {
        int a = idx / cols_in, c = idx - a * cols_in;
        int k = a - n, cc = c - n;
        int gy0 = min(H - 1, max(0, y0 + k));
        int gy1 = min(H - 1, y0 + k + 32);
        int gx = min(W - 1, max(0, x0 + cc));
        sB[(k + 10) * SS + (cc + 10)] =
            __floats2half2_rn(src[gy0 * W + gx], src[gy1 * W + gx]);
    }
    __syncthreads();

    // Work-item mapping (fixed per thread): 17 strips of 9 cols x up to 50 bases.
    const int kb1 = t / 17, st1 = t - kb1 * 17;
    const int t2 = t + NT;
    const int kb2 = t2 / 17, st2 = t2 - kb2 * 17;
    const bool yTop = (y0 == 0), yBot = (y0 + TY == H);
    const bool xL = (x0 == 0), xR = (x0 + TX == W);

    for (int d = 0; d < n; d++) {
        const int h = n - d;              // input halo
        const int g = h - 1;              // output halo
        const int bases_out = 32 + 2 * g;
        const int cols_out = 128 + 2 * g;

        // Compute to registers (in-place update: all reads before any write).
        __half2 ra[9], rb[9];
        const bool a1 = (kb1 < bases_out), a2 = (kb2 < bases_out);
        int k1 = 0, k2 = 0, c1 = 0, c2 = 0;
        if (a1) {
            k1 = kb1 - g;
            c1 = -g + min(9 * st1, cols_out - 9);
            const __half2* p = sB + (k1 - 1 + 10) * SS + (c1 - 1 + 10);
            med_strip9(p, p + SS, p + 2 * SS, ra);
        }
        if (a2) {
            k2 = kb2 - g;
            c2 = -g + min(9 * st2, cols_out - 9);
            const __half2* p = sB + (k2 - 1 + 10) * SS + (c2 - 1 + 10);
            med_strip9(p, p + SS, p + 2 * SS, rb);
        }
        __syncthreads();

        if (a1) {
            __half2* q = sB + (k1 + 10) * SS + (c1 + 10);
#pragma unroll
            for (int i = 0; i < 9; i++) q[i] = ra[i];
        }
        if (a2) {
            __half2* q = sB + (k2 + 10) * SS + (c2 + 10);
#pragma unroll
            for (int i = 0; i < 9; i++) q[i] = rb[i];
        }
        __syncthreads();

        // ---- Mid-level edge repair: out-of-image halo entries := clamped copy.
        // Row repair touches only in-image cols; col repair composes row clamp
        // per pair-half from pre-repair values -> target sets disjoint, no race.
        if (g > 0) {
            if (yTop | yBot | xL | xR) {
                const int clo = xL ? 0 : -g;
                const int chi = xR ? 127 : 127 + g;
                const int cw = chi - clo + 1;
                if (yTop) {                 // rows <0 := row 0 (low lanes)
                    for (int idx = t; idx < g * cw; idx += NT) {
                        int kk = -g + idx / cw, c = clo + idx % cw;
                        __half2* e = sB + (kk + 10) * SS + (c + 10);
                        __half2 s0 = sB[10 * SS + (c + 10)];
                        *e = __halves2half2(__low2half(s0), __high2half(*e));
                    }
                }
                if (yBot) {                 // rows >=64 := row 63 (high lanes)
                    for (int idx = t; idx < g * cw; idx += NT) {
                        int kk = 32 + idx / cw, c = clo + idx % cw;
                        __half2* e = sB + (kk + 10) * SS + (c + 10);
                        __half2 s1 = sB[41 * SS + (c + 10)];
                        *e = __halves2half2(__low2half(*e), __high2half(s1));
                    }
                }
                if (xL | xR) {              // cols outside := col 0 / 127
                    const int kcnt = 32 + 2 * g;
                    const int sides = (xL && xR) ? 2 : 1;
                    for (int idx = t; idx < sides * g * kcnt; idx += NT) {
                        int side = xL ? (idx >= g * kcnt) : 1;
                        int r = xL ? (idx - side * g * kcnt) : idx;
                        int kk = -g + r % kcnt;
                        int cc = r / kcnt;                 // 0..g-1
                        int ct = side ? (128 + cc) : (-1 - cc);
                        int cs = side ? 127 : 0;
                        __half2 s = sB[(kk + 10) * SS + (cs + 10)];
                        __half lo = __low2half(s), hi = __high2half(s);
                        if (yTop && kk < 0)
                            lo = __low2half(sB[10 * SS + (cs + 10)]);
                        if (yBot && kk >= 32)
                            hi = __high2half(sB[41 * SS + (cs + 10)]);
                        sB[(kk + 10) * SS + (ct + 10)] = __halves2half2(lo, hi);
                    }
                }
            }
            __syncthreads();
        }
    }

    // ---- Coalesced fp32 epilogue from the final tile (bases 0..31, cols 0..127).
    for (int idx = t; idx < TY * (TX / 4); idx += NT) {
        int y = idx >> 5, cq = idx & 31;
        const __half2* e = sB + ((y & 31) + 10) * SS + (4 * cq + 10);
        float4 v;
        if (y >> 5)
            v = make_float4(__high2float(e[0]), __high2float(e[1]),
                            __high2float(e[2]), __high2float(e[3]));
        else
            v = make_float4(__low2float(e[0]), __low2float(e[1]),
                            __low2float(e[2]), __low2float(e[3]));
        ((float4*)(dst + (size_t)(y0 + y) * W + x0))[cq] = v;
    }
}

extern "C" void kernel_launch(void* const* d_in, const int* in_sizes, int n_in,
                              void* d_out, int out_size)
{
    const float* x = (const float*)d_in[0];
    const int* traw = (const int*)d_in[1];
    float* out = (float*)d_out;

    prep_t<<<1, 32>>>(traw);
    medianAll<<<dim3(W / TX, H / TY, BATCH), NT>>>(x, out);   // (4, 8, 32)
}